// round 13
// baseline (speedup 1.0000x reference)
#include <cuda_runtime.h>
#include <cuda_fp16.h>
#include <cstdint>

#define B_  32
#define O_  256
#define HW  625
#define WO  25
#define CKK 12544            // 256*49 = 112*112 exactly

#define THREADS 256          // 8 warps: 4(M) x 2(N), warp tile 32 x 80
#define NITER   112          // dense k chunks of 112
#define KSTEPS  7
#define PITCH   120
#define PITCHB  240
#define A_TILE  30720        // 128 * 240
#define B_TILE  38400        // 160 * 240

#define XCH     448          // 14 rows * 32 floats per ring slot
#define XSTG    434          // 14 * 31 staged floats per channel
#define XSLOTS  8

#define SM_A    0            // 2 * 30720 = 61440
#define SM_B    61440        // 2 * 38400 -> 138240
#define SM_XR   138240       // 8 * 448 * 4 = 14336 -> 152576
#define SM_KM   152576       // 2 * 448 -> 153472
#define SM_TI   153472       // 2 * 448 -> 154368
#define SM_RTAB 154368       // 160 ints -> 155008
#define SMEM_DYN 155136

// Precomputed fp16 weights (x256), dense k slices: [t][iter][o 128][k 120]
__device__ __half g_W[2][NITER][128][PITCH];

__device__ __forceinline__ uint32_t smem_u32(const void* p) {
    uint32_t a;
    asm("{ .reg .u64 t; cvta.to.shared.u64 t, %1; cvt.u32.u64 %0, t; }" : "=r"(a) : "l"(p));
    return a;
}
__device__ __forceinline__ void ldsm4(uint32_t* r, uint32_t addr) {
    asm volatile("ldmatrix.sync.aligned.m8n8.x4.shared.b16 {%0,%1,%2,%3}, [%4];"
                 : "=r"(r[0]), "=r"(r[1]), "=r"(r[2]), "=r"(r[3]) : "r"(addr));
}
__device__ __forceinline__ void mma_f16(float* d, const uint32_t* a, const uint32_t* b) {
    asm volatile("mma.sync.aligned.m16n8k16.row.col.f32.f16.f16.f32 "
                 "{%0,%1,%2,%3}, {%4,%5,%6,%7}, {%8,%9}, {%0,%1,%2,%3};"
                 : "+f"(d[0]), "+f"(d[1]), "+f"(d[2]), "+f"(d[3])
                 : "r"(a[0]), "r"(a[1]), "r"(a[2]), "r"(a[3]), "r"(b[0]), "r"(b[1]));
}
#define CP16(dst, src) \
    asm volatile("cp.async.cg.shared.global [%0], [%1], 16;" :: "r"(dst), "l"(src) : "memory")
#define CP_COMMIT() asm volatile("cp.async.commit_group;" ::: "memory")
#define CP_WAIT0()  asm volatile("cp.async.wait_group 0;" ::: "memory")

// dense slice copy: g_W[t][gi][o][k] = 256 * w[(t*128+o)*CKK + gi*112 + k]
__global__ void precompute_w(const float* __restrict__ w) {
    long idx = (long)blockIdx.x * 256 + threadIdx.x;   // [t][gi][o][k<120]
    int k  = idx % PITCH;
    int o  = (idx / PITCH) & 127;
    int gi = (int)((idx / (PITCH * 128)) % NITER);
    int t  = (int)(idx / ((long)PITCH * 128 * NITER));
    if (t >= 2) return;
    float v = (k < 112) ? w[(size_t)(t * 128 + o) * CKK + gi * 112 + k] * 256.f : 0.f;
    g_W[t][gi][o][k] = __float2half_rn(v);
}

__global__ __launch_bounds__(THREADS, 1)
void dwconv_hmma10(const float* __restrict__ x, const float* __restrict__ kern,
                   const float* __restrict__ bias, float* __restrict__ out)
{
    extern __shared__ __align__(128) char smem[];
    const uint32_t sbase = smem_u32(smem);

    const int tid = threadIdx.x, wid = tid >> 5, lid = tid & 31;
    const int mw = wid >> 1, nw = wid & 1;
    const int blk = blockIdx.x;
    const int pt = blk & 3, t = (blk >> 2) & 1, b = blk >> 3;
    const int p0 = pt * 160, o0 = t * 128;
    const int h0 = p0 / WO;

    int* rtab = (int*)(smem + SM_RTAB);
    if (tid < 160) {
        int pg = p0 + tid;
        rtab[tid] = (pg < HW) ? ((pg / WO) - h0) * 32 + (pg % WO) : -1;
    }

    const float* xb = x    + (size_t)b * 256 * 961;
    const float* kb = kern + (size_t)b * CKK;   // kern is dense [256*49] per batch

    // stage km (dense copy) + offset table for iter q into buf q&1
    auto stage_kmti = [&](int q) {
        float* km = (float*)(smem + SM_KM + (q & 1) * 448);
        int*   ti = (int*)(smem + SM_TI + (q & 1) * 448);
        if (tid < NITER) {
            km[tid] = kb[(size_t)q * 112 + tid];
            int r0  = (14 * (q % 7)) % 49;
            int csg = (16 * q) / 7;              // first channel of this iter
            int rr  = r0 + tid;                  // <= 153
            int dc  = (rr >= 49) + (rr >= 98) + (rr >= 147);
            int rl  = rr - dc * 49;
            int ki  = rl / 7, kj = rl - ki * 7;
            ti[tid] = ((csg + dc) & 7) * XCH + ki * 32 + kj;
        }
    };
    // direct channel stage (prologue only): channel cc -> ring slot cc&7
    auto stage_ch = [&](int cc) {
        float* xs = (float*)(smem + SM_XR) + (cc & 7) * XCH;
#pragma unroll
        for (int i = 0; i < 2; i++) {
            int id = tid + i * 256;
            if (id < XSTG) {
                float v = (h0 * 31 + id < 961) ? xb[(size_t)cc * 961 + h0 * 31 + id] : 0.f;
                xs[(id / 31) * 32 + (id % 31)] = v;
            }
        }
    };
    auto cpasync_A = [&](int gg) {
        const char* src = (const char*)&g_W[t][gg][0][0];
        uint32_t dst = sbase + SM_A + (gg & 1) * A_TILE;
#pragma unroll
        for (int i = 0; i < 8; i++) {
            int idx = i * 256 + tid;
            if (idx < 1920) CP16(dst + idx * 16, src + idx * 16);
        }
        CP_COMMIT();
    };
    // dense B build: 35 warp-tasks = 5 p-grp x 7 k-chunks (16 k each)
    auto build_B = [&](int s) {
        char* bt = smem + SM_B + s * B_TILE;
        const float* km = (const float*)(smem + SM_KM + s * 448);
        const int*   ti = (const int*)(smem + SM_TI + s * 448);
        const float* xr = (const float*)(smem + SM_XR);
#pragma unroll
        for (int it = 0; it < 5; it++) {
            int wt = it * 8 + wid;
            if (wt < 35) {
                int pg5 = wt / 7, kc = wt - pg5 * 7;
                int p = pg5 * 32 + lid;
                int rb = rtab[p];
                uint4 v0 = make_uint4(0, 0, 0, 0), v1 = make_uint4(0, 0, 0, 0);
                if (rb >= 0) {
                    const int4 t0 = *(const int4*)(ti + kc * 16);
                    const int4 t1 = *(const int4*)(ti + kc * 16 + 4);
                    const int4 t2 = *(const int4*)(ti + kc * 16 + 8);
                    const int4 t3 = *(const int4*)(ti + kc * 16 + 12);
                    const float4 k0 = *(const float4*)(km + kc * 16);
                    const float4 k1 = *(const float4*)(km + kc * 16 + 4);
                    const float4 k2 = *(const float4*)(km + kc * 16 + 8);
                    const float4 k3 = *(const float4*)(km + kc * 16 + 12);
                    __half2 h0v = __floats2half2_rn(xr[t0.x + rb] * k0.x, xr[t0.y + rb] * k0.y);
                    __half2 h1v = __floats2half2_rn(xr[t0.z + rb] * k0.z, xr[t0.w + rb] * k0.w);
                    __half2 h2v = __floats2half2_rn(xr[t1.x + rb] * k1.x, xr[t1.y + rb] * k1.y);
                    __half2 h3v = __floats2half2_rn(xr[t1.z + rb] * k1.z, xr[t1.w + rb] * k1.w);
                    __half2 h4v = __floats2half2_rn(xr[t2.x + rb] * k2.x, xr[t2.y + rb] * k2.y);
                    __half2 h5v = __floats2half2_rn(xr[t2.z + rb] * k2.z, xr[t2.w + rb] * k2.w);
                    __half2 h6v = __floats2half2_rn(xr[t3.x + rb] * k3.x, xr[t3.y + rb] * k3.y);
                    __half2 h7v = __floats2half2_rn(xr[t3.z + rb] * k3.z, xr[t3.w + rb] * k3.w);
                    v0 = make_uint4(*(uint32_t*)&h0v, *(uint32_t*)&h1v,
                                    *(uint32_t*)&h2v, *(uint32_t*)&h3v);
                    v1 = make_uint4(*(uint32_t*)&h4v, *(uint32_t*)&h5v,
                                    *(uint32_t*)&h6v, *(uint32_t*)&h7v);
                }
                *(uint4*)(bt + p * PITCHB + kc * 32)      = v0;
                *(uint4*)(bt + p * PITCHB + kc * 32 + 16) = v1;
            }
        }
    };

    // ---------- prologue ----------
    cpasync_A(0);
#pragma unroll
    for (int cc = 0; cc < 6; cc++) stage_ch(cc);   // windows of iters 0 and 1 (cs(1)=2 -> 2..5)
    stage_kmti(0);
    stage_kmti(1);
    __syncthreads();
    build_B(0);
    CP_WAIT0();

    float acc[2][10][4];
#pragma unroll
    for (int mi = 0; mi < 2; mi++)
#pragma unroll
        for (int j = 0; j < 10; j++)
#pragma unroll
            for (int q = 0; q < 4; q++) acc[mi][j][q] = 0.f;

    const uint32_t apat = (uint32_t)((mw * 32 + (lid & 15)) * PITCHB + (lid >> 4) * 16);
    const uint32_t bpat = (uint32_t)((nw * 80 + (lid & 7) + ((lid & 16) ? 8 : 0)) * PITCHB
                                     + ((lid & 8) ? 16 : 0));

    // ---------- main loop: ONE sync per iter ----------
#pragma unroll 1
    for (int g = 0; g < NITER; g++) {
        const int buf = g & 1;
        __syncthreads();   // publishes: B(g), A(g), ring channels + km/ti for build(g+1)

        if (g + 1 < NITER) cpasync_A(g + 1);

        // prefetch x channels for window g+2: [cs(g+1)+4, min(cs(g+2)+3, 255)]
        int lo = 0, hi = -1;
        float xv[3][2];
        if (g + 2 < NITER) {
            lo = (16 * (g + 1)) / 7 + 4;
            hi = (16 * (g + 2)) / 7 + 3;
            if (hi > 255) hi = 255;
#pragma unroll
            for (int ci = 0; ci < 3; ci++) {
                int cc = lo + ci;
                xv[ci][0] = xv[ci][1] = 0.f;
                if (cc <= hi) {
#pragma unroll
                    for (int i = 0; i < 2; i++) {
                        int id = tid + i * 256;
                        if (id < XSTG && h0 * 31 + id < 961)
                            xv[ci][i] = xb[(size_t)cc * 961 + h0 * 31 + id];
                    }
                }
            }
        }

        // MMA(g): warp tile 32(M) x 80(N)
        {
            const uint32_t ab = sbase + SM_A + buf * A_TILE + apat;
            const uint32_t bb = sbase + SM_B + buf * B_TILE + bpat;
#pragma unroll
            for (int k = 0; k < KSTEPS; k++) {
                uint32_t A0[4], A1[4], Bv[20];
                ldsm4(A0, ab + k * 32);
                ldsm4(A1, ab + 3840 + k * 32);
#pragma unroll
                for (int j5 = 0; j5 < 5; j5++) ldsm4(&Bv[j5 * 4], bb + j5 * 3840 + k * 32);
#pragma unroll
                for (int j = 0; j < 10; j++) {
                    const uint32_t* bf = &Bv[(j >> 1) * 4 + (j & 1) * 2];
                    mma_f16(acc[0][j], A0, bf);
                    mma_f16(acc[1][j], A1, bf);
                }
            }
        }

        if (g + 1 < NITER) build_B((g + 1) & 1);

        // store prefetched channels into ring + stage km/ti for iter g+2
        if (g + 2 < NITER) {
#pragma unroll
            for (int ci = 0; ci < 3; ci++) {
                int cc = lo + ci;
                if (cc <= hi) {
                    float* xs = (float*)(smem + SM_XR) + (cc & 7) * XCH;
#pragma unroll
                    for (int i = 0; i < 2; i++) {
                        int id = tid + i * 256;
                        if (id < XSTG) xs[(id / 31) * 32 + (id % 31)] = xv[ci][i];
                    }
                }
            }
            stage_kmti(g + 2);
        }

        CP_WAIT0();        // A(g+1) arrived
    }

    // ---------- epilogue ----------
    const float s = 1.0f / 256.0f;
#pragma unroll
    for (int mi = 0; mi < 2; mi++) {
        int o = o0 + mw * 32 + mi * 16 + (lid >> 2);
        float bv0 = __ldg(bias + o);
        float bv1 = __ldg(bias + o + 8);
        float* r0 = out + ((size_t)b * O_ + o) * HW;
        float* r1 = r0 + 8 * HW;
#pragma unroll
        for (int j = 0; j < 10; j++) {
            int p = p0 + nw * 80 + j * 8 + 2 * (lid & 3);
            if (p < HW)     r0[p]     = acc[mi][j][0] * s + bv0;
            if (p + 1 < HW) r0[p + 1] = acc[mi][j][1] * s + bv0;
            if (p < HW)     r1[p]     = acc[mi][j][2] * s + bv1;
            if (p + 1 < HW) r1[p + 1] = acc[mi][j][3] * s + bv1;
        }
    }
}

extern "C" void kernel_launch(void* const* d_in, const int* in_sizes, int n_in,
                              void* d_out, int out_size) {
    const float* x      = (const float*)d_in[0];
    const float* kernel = (const float*)d_in[1];
    const float* weight = (const float*)d_in[2];
    const float* bias   = (const float*)d_in[3];
    float* out = (float*)d_out;

    cudaFuncSetAttribute(dwconv_hmma10, cudaFuncAttributeMaxDynamicSharedMemorySize, SMEM_DYN);

    // 2 * 112 * 128 * 120 = 3,440,640 elements / 256 = 13440 blocks
    precompute_w<<<13440, 256>>>(weight);
    dwconv_hmma10<<<256, THREADS, SMEM_DYN>>>(x, kernel, bias, out);
}